// round 3
// baseline (speedup 1.0000x reference)
#include <cuda_runtime.h>
#include <cuda_fp16.h>
#include <cstdint>

// QuantLinearMarlin: out[16,8192] = f16(x[16,8192] @ dequant(qweight, scales)) + bias
// INT4 symmetric (zp=8), group 128. Harness buffers are fp32 (fp16-exact values).
//
// Single fused kernel:
//   phase 1: convert own x-chunk fp32->fp16 into padded smem
//   phase 2: HMMA m16n8k16 GEMM, in-register INT4 dequant (magic LOP3,
//            Sterbenz-exact -8), split-K=16, fp32 partials to workspace
//   phase 3: last block per n-tile reduces splits in fixed order, applies
//            fp16 rounding + bias, writes fp32 output, resets counter.

#define MM 16
#define KK 8192
#define NN 8192
#define GROUPSZ 128
#define KSPLIT 16
#define KCHUNK (KK / KSPLIT)                 // 512
#define GROUPS_PER_CHUNK (KCHUNK / GROUPSZ)  // 4
#define STEPS_PER_GROUP (GROUPSZ / 16)       // 8
#define NTILE 256                            // cols per block
#define NT (NN / NTILE)                      // 32 n-tiles
#define XS_STRIDE 528                        // halves; 264 words == 8 mod 32 (bank-safe)

// fp32 partial sums: [KSPLIT][M][N] = 8 MB
__device__ float g_ws[KSPLIT * MM * NN];
// split-arrival counters per n-tile (zero-init; reducer resets after use)
__device__ unsigned g_cnt[NT];

static __device__ __forceinline__ __half2 u32_as_half2(uint32_t u) {
    return *reinterpret_cast<__half2*>(&u);
}
static __device__ __forceinline__ uint32_t half2_as_u32(__half2 h) {
    return *reinterpret_cast<uint32_t*>(&h);
}

static __device__ __forceinline__ void mma_16816(float c[4],
                                                 uint32_t a0, uint32_t a1, uint32_t a2, uint32_t a3,
                                                 uint32_t b0, uint32_t b1) {
    asm volatile(
        "mma.sync.aligned.m16n8k16.row.col.f32.f16.f16.f32 "
        "{%0,%1,%2,%3}, {%4,%5,%6,%7}, {%8,%9}, {%0,%1,%2,%3};\n"
        : "+f"(c[0]), "+f"(c[1]), "+f"(c[2]), "+f"(c[3])
        : "r"(a0), "r"(a1), "r"(a2), "r"(a3), "r"(b0), "r"(b1));
}

// Grid: (NT, KSPLIT). Block: 256 threads = 8 warps; warp w covers 32 cols.
//
// k-row permutation per 16-k tile (words kb, kb+1; tg=lane&3, tg2=tg>>1, e=tg&1):
//   lane reads word kb+tg2, u = w >> 8e. mma-k rows -> actual k offsets:
//     2tg   -> 8*tg2+2e      2tg+1 -> 8*tg2+2e+4
//     2tg+8 -> 8*tg2+2e+1    2tg+9 -> 8*tg2+2e+5
//   b0 = fp16x2(u nibbles 0,4), b1 = fp16x2(u nibbles 1,5).
//   A fragments follow the same permutation via LDS.128 + 2 PRMT per row.
__global__ __launch_bounds__(256) void qlinear_fused(
    const float* __restrict__ x,       // [16][8192] f32 (fp16-exact)
    const int*   __restrict__ qw,      // [1024][8192] int32 (8 nibbles along K)
    const float* __restrict__ scales,  // [64][8192] f32 (fp16-exact)
    const float* __restrict__ bias,    // [8192] f32 (fp16-exact)
    float*       __restrict__ out)     // [16][8192] f32
{
    __shared__ __half xs[MM * XS_STRIDE];   // 16.5 KB
    __shared__ unsigned s_last;

    const int tid    = threadIdx.x;
    const int ntile  = blockIdx.x;
    const int split  = blockIdx.y;
    const int kchunk = split * KCHUNK;

    // ---- phase 1: convert x chunk (16 rows x 512 f32) to fp16 smem ----
    {
        const int row = tid >> 4;          // 16 threads per row
        const int c0  = (tid & 15) * 4;    // float4 slot; +64 per iter
        const float* xr = x + (size_t)row * KK + kchunk;
        __half* xsr = xs + row * XS_STRIDE;
        #pragma unroll
        for (int i = 0; i < 8; ++i) {
            int c = c0 + i * 64;
            float4 v = *reinterpret_cast<const float4*>(xr + c);
            __half2 lo = __floats2half2_rn(v.x, v.y);
            __half2 hi = __floats2half2_rn(v.z, v.w);
            *reinterpret_cast<uint2*>(xsr + c) =
                make_uint2(half2_as_u32(lo), half2_as_u32(hi));
        }
    }
    __syncthreads();

    // ---- phase 2: GEMM over this k-chunk ----
    const int warp = tid >> 5;
    const int lane = tid & 31;
    const int g    = lane >> 2;
    const int tg   = lane & 3;
    const int tg2  = tg >> 1;
    const int tge  = tg & 1;

    const int nb = ntile * NTILE + warp * 32;   // warp col base

    const __half* axs0 = xs + g * XS_STRIDE + tg2 * 8;
    const __half* axs1 = xs + (g + 8) * XS_STRIDE + tg2 * 8;
    const int* pb = qw + ((size_t)(kchunk >> 3) + tg2) * NN + nb + g;
    const float* psc = scales + (size_t)(kchunk / GROUPSZ) * NN + nb + g;

    float c[4][4];
    #pragma unroll
    for (int j = 0; j < 4; ++j)
        #pragma unroll
        for (int i = 0; i < 4; ++i) c[j][i] = 0.0f;

    const __half2 h1032 = u32_as_half2(0x64086408u);  // (1032, 1032)

    #pragma unroll 1
    for (int grp = 0; grp < GROUPS_PER_CHUNK; ++grp) {
        __half2 s2[4];
        #pragma unroll
        for (int j = 0; j < 4; ++j)
            s2[j] = __half2half2(__float2half_rn(psc[8 * j]));  // exact
        psc += NN;

        #pragma unroll
        for (int it = 0; it < STEPS_PER_GROUP; ++it) {
            const int step = grp * STEPS_PER_GROUP + it;
            // ---- A fragments from smem ----
            uint4 va = *reinterpret_cast<const uint4*>(axs0 + step * 16);
            uint4 vb = *reinterpret_cast<const uint4*>(axs1 + step * 16);
            uint32_t xa = tge ? va.y : va.x;   // halves (2e, 2e+1)
            uint32_t xb = tge ? va.w : va.z;   // halves (2e+4, 2e+5)
            uint32_t ya = tge ? vb.y : vb.x;
            uint32_t yb = tge ? vb.w : vb.z;
            uint32_t a0 = __byte_perm(xa, xb, 0x5410);
            uint32_t a1 = __byte_perm(ya, yb, 0x5410);
            uint32_t a2 = __byte_perm(xa, xb, 0x7632);
            uint32_t a3 = __byte_perm(ya, yb, 0x7632);

            // ---- B: dequant 4 column-blocks ----
            #pragma unroll
            for (int j = 0; j < 4; ++j) {
                uint32_t w = (uint32_t)pb[8 * j];
                uint32_t u = w >> (tge * 8);
                uint32_t q0 = (u & 0x000F000Fu) | 0x64006400u;         // 1024+v
                uint32_t q1 = ((u >> 4) & 0x000F000Fu) | 0x64006400u;
                __half2 b0 = __hmul2(__hsub2(u32_as_half2(q0), h1032), s2[j]);
                __half2 b1 = __hmul2(__hsub2(u32_as_half2(q1), h1032), s2[j]);
                mma_16816(c[j], a0, a1, a2, a3, half2_as_u32(b0), half2_as_u32(b1));
            }
            pb += 2 * NN;
        }
    }

    // ---- store fp32 partials ----
    float* wsp = g_ws + (size_t)split * MM * NN;
    #pragma unroll
    for (int j = 0; j < 4; ++j) {
        int col = nb + 8 * j + 2 * tg;
        *reinterpret_cast<float2*>(wsp + (size_t)g * NN + col)       = make_float2(c[j][0], c[j][1]);
        *reinterpret_cast<float2*>(wsp + (size_t)(g + 8) * NN + col) = make_float2(c[j][2], c[j][3]);
    }

    // ---- phase 3: last split block per n-tile reduces ----
    __threadfence();
    __syncthreads();
    if (tid == 0)
        s_last = (atomicAdd(&g_cnt[ntile], 1u) == KSPLIT - 1) ? 1u : 0u;
    __syncthreads();
    if (!s_last) return;
    __threadfence();  // acquire side

    // 16 rows x 256 cols = 2048 float2 outputs; 8 per thread
    #pragma unroll
    for (int i = 0; i < 8; ++i) {
        int lin = i * 256 + tid;              // float2 index within tile
        int m   = lin >> 7;                   // 128 float2 per row
        int col = ntile * NTILE + ((lin & 127) << 1);
        size_t off = (size_t)m * NN + col;
        float ax = 0.0f, ay = 0.0f;
        #pragma unroll
        for (int s = 0; s < KSPLIT; ++s) {
            float2 v = *reinterpret_cast<const float2*>(g_ws + (size_t)s * MM * NN + off);
            ax += v.x; ay += v.y;
        }
        float bx = bias[col], by = bias[col + 1];
        // fp16 semantics: h = f16(dot); out = f16(h + b)
        float hx = __half2float(__float2half_rn(ax));
        float hy = __half2float(__float2half_rn(ay));
        float ox = __half2float(__float2half_rn(hx + bx));
        float oy = __half2float(__float2half_rn(hy + by));
        *reinterpret_cast<float2*>(out + off) = make_float2(ox, oy);
    }

    if (tid == 0) g_cnt[ntile] = 0;  // replay-safe reset
}

extern "C" void kernel_launch(void* const* d_in, const int* in_sizes, int n_in,
                              void* d_out, int out_size) {
    const float* x      = (const float*)d_in[0];
    const int*   qw     = (const int*)d_in[1];
    const float* scales = (const float*)d_in[2];
    const float* bias   = (const float*)d_in[3];
    float* out = (float*)d_out;

    dim3 grid(NT, KSPLIT);
    qlinear_fused<<<grid, 256>>>(x, qw, scales, bias, out);
}

// round 4
// speedup vs baseline: 1.1747x; 1.1747x over previous
#include <cuda_runtime.h>
#include <cuda_fp16.h>
#include <cstdint>

// QuantLinearMarlin: out[16,8192] = f16(x @ dequant(qweight, scales)) + bias
// INT4 symmetric (zp=8), group 128. Harness buffers are fp32 (fp16-exact).
//
// Fused kernel, column-interleaved mma mapping:
//   mma block j (j=0..3), mma col n (0..7)  <->  physical col nb + 4n + j
//   => lane (quad g) loads ONE uint4 (4 adjacent qweight words = its 4 j-blocks)
//      per 16-k step, fully coalesced (2x128B lines per warp instr), and one
//      float4 of scales per group. B loads are double-buffered (MLP=4).
// Split-K=16 into fp32 workspace (permuted tile layout, vector stores);
// last-arriving block reduces in fixed order, un-permutes, applies fp16
// rounding semantics + bias, writes fp32 output, resets the counter.

#define MM 16
#define KK 8192
#define NN 8192
#define GROUPSZ 128
#define KSPLIT 16
#define KCHUNK (KK / KSPLIT)                 // 512
#define GROUPS_PER_CHUNK (KCHUNK / GROUPSZ)  // 4
#define NTILE 256
#define NT (NN / NTILE)                      // 32
#define XS_STRIDE 528                        // halves; bank-safe row stride

__device__ float g_ws[KSPLIT * MM * NN];     // 8 MB fp32 partials
__device__ unsigned g_cnt[NT];

static __device__ __forceinline__ __half2 u32_as_half2(uint32_t u) {
    return *reinterpret_cast<__half2*>(&u);
}
static __device__ __forceinline__ uint32_t half2_as_u32(__half2 h) {
    return *reinterpret_cast<uint32_t*>(&h);
}

static __device__ __forceinline__ void mma_16816(float c[4],
                                                 uint32_t a0, uint32_t a1, uint32_t a2, uint32_t a3,
                                                 uint32_t b0, uint32_t b1) {
    asm volatile(
        "mma.sync.aligned.m16n8k16.row.col.f32.f16.f16.f32 "
        "{%0,%1,%2,%3}, {%4,%5,%6,%7}, {%8,%9}, {%0,%1,%2,%3};\n"
        : "+f"(c[0]), "+f"(c[1]), "+f"(c[2]), "+f"(c[3])
        : "r"(a0), "r"(a1), "r"(a2), "r"(a3), "r"(b0), "r"(b1));
}

// k-row permutation per 16-k tile (word rows kb, kb+1; tg=lane&3, tg2=tg>>1, e=tg&1):
//   lane uses word row kb+tg2, u = w >> 8e. mma-k -> actual k:
//     2tg -> 8tg2+2e   2tg+1 -> 8tg2+2e+4   2tg+8 -> 8tg2+2e+1   2tg+9 -> 8tg2+2e+5
//   b0 = fp16x2(u nib 0,4), b1 = fp16x2(u nib 1,5). A follows via LDS.128 + PRMT.
__global__ __launch_bounds__(256, 4) void qlinear_fused(
    const float* __restrict__ x,
    const int*   __restrict__ qw,
    const float* __restrict__ scales,
    const float* __restrict__ bias,
    float*       __restrict__ out)
{
    __shared__ __half xs[MM * XS_STRIDE];
    __shared__ unsigned s_last;

    const int tid    = threadIdx.x;
    const int ntile  = blockIdx.x;
    const int split  = blockIdx.y;
    const int kchunk = split * KCHUNK;

    // ---- phase 1: convert x chunk (16 x 512 f32) to fp16 smem ----
    {
        const int row = tid >> 4;
        const int c0  = (tid & 15) * 4;
        const float* xr = x + (size_t)row * KK + kchunk;
        __half* xsr = xs + row * XS_STRIDE;
        #pragma unroll
        for (int i = 0; i < 8; ++i) {
            int cc = c0 + i * 64;
            float4 v = *reinterpret_cast<const float4*>(xr + cc);
            __half2 lo = __floats2half2_rn(v.x, v.y);
            __half2 hi = __floats2half2_rn(v.z, v.w);
            *reinterpret_cast<uint2*>(xsr + cc) =
                make_uint2(half2_as_u32(lo), half2_as_u32(hi));
        }
    }
    __syncthreads();

    // ---- phase 2: GEMM ----
    const int warp = tid >> 5;
    const int lane = tid & 31;
    const int g    = lane >> 2;
    const int tg   = lane & 3;
    const int tg2  = tg >> 1;
    const int tge  = tg & 1;
    const int sh   = tge * 8;

    const int nbase = ntile * NTILE + warp * 32;

    const __half* axs0 = xs + g * XS_STRIDE + tg2 * 8;
    const __half* axs1 = xs + (g + 8) * XS_STRIDE + tg2 * 8;
    // B: uint4 at word row (kchunk/8 + 2*step + tg2), word col nbase + 4g
    const int* pb = qw + ((size_t)(kchunk >> 3) + tg2) * NN + nbase + 4 * g;
    const float* psc = scales + (size_t)(kchunk / GROUPSZ) * NN + nbase + 4 * g;

    float c[4][4];
    #pragma unroll
    for (int j = 0; j < 4; ++j)
        #pragma unroll
        for (int i = 0; i < 4; ++i) c[j][i] = 0.0f;

    const __half2 h1032 = u32_as_half2(0x64086408u);

    uint4 Ba[4], Bb[4];
    #pragma unroll
    for (int s = 0; s < 4; ++s)
        Ba[s] = *reinterpret_cast<const uint4*>(pb + (size_t)(2 * s) * NN);

    #pragma unroll 1
    for (int grp = 0; grp < GROUPS_PER_CHUNK; ++grp) {
        // scales for this group: 4 adjacent cols = the 4 j-blocks
        float4 sv = *reinterpret_cast<const float4*>(psc);
        psc += NN;
        __half2 s2[4];
        s2[0] = __half2half2(__float2half_rn(sv.x));
        s2[1] = __half2half2(__float2half_rn(sv.y));
        s2[2] = __half2half2(__float2half_rn(sv.z));
        s2[3] = __half2half2(__float2half_rn(sv.w));

        // prefetch steps 4..7 of this group
        #pragma unroll
        for (int s = 0; s < 4; ++s)
            Bb[s] = *reinterpret_cast<const uint4*>(pb + (size_t)(8 + 2 * s) * NN);

        // process steps 0..3 with Ba
        #pragma unroll
        for (int it = 0; it < 4; ++it) {
            const int step = grp * 8 + it;
            uint4 va = *reinterpret_cast<const uint4*>(axs0 + step * 16);
            uint4 vb = *reinterpret_cast<const uint4*>(axs1 + step * 16);
            uint32_t xa = tge ? va.y : va.x;
            uint32_t xb = tge ? va.w : va.z;
            uint32_t ya = tge ? vb.y : vb.x;
            uint32_t yb = tge ? vb.w : vb.z;
            uint32_t a0 = __byte_perm(xa, xb, 0x5410);
            uint32_t a1 = __byte_perm(ya, yb, 0x5410);
            uint32_t a2 = __byte_perm(xa, xb, 0x7632);
            uint32_t a3 = __byte_perm(ya, yb, 0x7632);
            const uint32_t* bw = reinterpret_cast<const uint32_t*>(&Ba[it]);
            #pragma unroll
            for (int j = 0; j < 4; ++j) {
                uint32_t u = bw[j] >> sh;
                uint32_t q0 = (u & 0x000F000Fu) | 0x64006400u;
                uint32_t q1 = ((u >> 4) & 0x000F000Fu) | 0x64006400u;
                __half2 b0 = __hmul2(__hsub2(u32_as_half2(q0), h1032), s2[j]);
                __half2 b1 = __hmul2(__hsub2(u32_as_half2(q1), h1032), s2[j]);
                mma_16816(c[j], a0, a1, a2, a3, half2_as_u32(b0), half2_as_u32(b1));
            }
        }

        // prefetch steps 0..3 of next group (harmless re-read on last group)
        const int nxt = (grp + 1 < GROUPS_PER_CHUNK) ? 16 : 0;
        #pragma unroll
        for (int s = 0; s < 4; ++s)
            Ba[s] = *reinterpret_cast<const uint4*>(pb + (size_t)(nxt + 2 * s) * NN);

        // process steps 4..7 with Bb
        #pragma unroll
        for (int it = 0; it < 4; ++it) {
            const int step = grp * 8 + 4 + it;
            uint4 va = *reinterpret_cast<const uint4*>(axs0 + step * 16);
            uint4 vb = *reinterpret_cast<const uint4*>(axs1 + step * 16);
            uint32_t xa = tge ? va.y : va.x;
            uint32_t xb = tge ? va.w : va.z;
            uint32_t ya = tge ? vb.y : vb.x;
            uint32_t yb = tge ? vb.w : vb.z;
            uint32_t a0 = __byte_perm(xa, xb, 0x5410);
            uint32_t a1 = __byte_perm(ya, yb, 0x5410);
            uint32_t a2 = __byte_perm(xa, xb, 0x7632);
            uint32_t a3 = __byte_perm(ya, yb, 0x7632);
            const uint32_t* bw = reinterpret_cast<const uint32_t*>(&Bb[it]);
            #pragma unroll
            for (int j = 0; j < 4; ++j) {
                uint32_t u = bw[j] >> sh;
                uint32_t q0 = (u & 0x000F000Fu) | 0x64006400u;
                uint32_t q1 = ((u >> 4) & 0x000F000Fu) | 0x64006400u;
                __half2 b0 = __hmul2(__hsub2(u32_as_half2(q0), h1032), s2[j]);
                __half2 b1 = __hmul2(__hsub2(u32_as_half2(q1), h1032), s2[j]);
                mma_16816(c[j], a0, a1, a2, a3, half2_as_u32(b0), half2_as_u32(b1));
            }
        }

        pb += 16 * (size_t)NN;
    }

    // ---- store fp32 partials in PERMUTED tile layout ----
    // element (j, mma-col n=2tg+i, row g/g+8) stored at pcol = warp*32 + 8j + 2tg + i
    float* wsp = g_ws + (size_t)split * MM * NN + ntile * NTILE;
    #pragma unroll
    for (int j = 0; j < 4; ++j) {
        int pcol = warp * 32 + 8 * j + 2 * tg;
        *reinterpret_cast<float2*>(wsp + (size_t)g * NN + pcol)       = make_float2(c[j][0], c[j][1]);
        *reinterpret_cast<float2*>(wsp + (size_t)(g + 8) * NN + pcol) = make_float2(c[j][2], c[j][3]);
    }

    // ---- phase 3: last split block reduces + un-permutes ----
    __threadfence();
    __syncthreads();
    if (tid == 0)
        s_last = (atomicAdd(&g_cnt[ntile], 1u) == KSPLIT - 1) ? 1u : 0u;
    __syncthreads();
    if (!s_last) return;
    __threadfence();

    #pragma unroll
    for (int i = 0; i < 8; ++i) {
        int lin  = i * 256 + tid;             // float2 index in permuted tile
        int m    = lin >> 7;
        int pcol = (lin & 127) << 1;
        size_t poff = (size_t)m * NN + ntile * NTILE + pcol;
        float ax = 0.0f, ay = 0.0f;
        #pragma unroll
        for (int s = 0; s < KSPLIT; ++s) {
            float2 v = *reinterpret_cast<const float2*>(g_ws + (size_t)s * MM * NN + poff);
            ax += v.x; ay += v.y;
        }
        // inverse permutation: pcol -> physical cols p0 (i=0) and p0+4 (i=1)
        int r  = pcol & 31;
        int w  = pcol >> 5;
        int jj = r >> 3;
        int tt = (r & 7) >> 1;
        int p0 = ntile * NTILE + w * 32 + 8 * tt + jj;
        float bx = bias[p0], by = bias[p0 + 4];
        float hx = __half2float(__float2half_rn(ax));
        float hy = __half2float(__float2half_rn(ay));
        out[(size_t)m * NN + p0]     = __half2float(__float2half_rn(hx + bx));
        out[(size_t)m * NN + p0 + 4] = __half2float(__float2half_rn(hy + by));
    }

    if (tid == 0) g_cnt[ntile] = 0;  // replay-safe reset
}

extern "C" void kernel_launch(void* const* d_in, const int* in_sizes, int n_in,
                              void* d_out, int out_size) {
    const float* x      = (const float*)d_in[0];
    const int*   qw     = (const int*)d_in[1];
    const float* scales = (const float*)d_in[2];
    const float* bias   = (const float*)d_in[3];
    float* out = (float*)d_out;

    dim3 grid(NT, KSPLIT);
    qlinear_fused<<<grid, 256>>>(x, qw, scales, bias, out);
}